// round 5
// baseline (speedup 1.0000x reference)
#include <cuda_runtime.h>
#include <math.h>
#include <stdint.h>
#include <float.h>

#define MAXB  128
#define CAP   4096
#define NBINS 2048
#define NT    1024

// Global scratch (no allocations allowed)
__device__ float g_sum[MAXB];
__device__ float g_shift[MAXB];
__device__ int   g_cnt[MAXB];
__device__ float g_cval[MAXB * CAP];
__device__ int   g_cidx[MAXB * CAP];

__device__ __forceinline__ int bin_of(float x) {
    int b = (int)floorf((x + 32.0f) * 32.0f);   // width 1/32 over [-32, 32]
    b = b < 0 ? 0 : b;
    return b > (NBINS - 1) ? (NBINS - 1) : b;
}

__device__ __forceinline__ float warp_red_sum(float v) {
    #pragma unroll
    for (int o = 16; o; o >>= 1) v += __shfl_xor_sync(0xffffffffu, v, o);
    return v;
}
__device__ __forceinline__ float warp_red_max(float v) {
    #pragma unroll
    for (int o = 16; o; o >>= 1) v = fmaxf(v, __shfl_xor_sync(0xffffffffu, v, o));
    return v;
}

__device__ __forceinline__ float block_incl_scan(float v, float* wsum, int lane, int wid) {
    #pragma unroll
    for (int off = 1; off < 32; off <<= 1) {
        float n = __shfl_up_sync(0xffffffffu, v, off);
        if (lane >= off) v += n;
    }
    __syncthreads();
    if (lane == 31) wsum[wid] = v;
    __syncthreads();
    if (wid == 0) {
        float w = wsum[lane];
        #pragma unroll
        for (int off = 1; off < 32; off <<= 1) {
            float n = __shfl_up_sync(0xffffffffu, w, off);
            if (lane >= off) w += n;
        }
        wsum[lane] = w;
    }
    __syncthreads();
    return v + (wid ? wsum[wid - 1] : 0.f);
}

__device__ __forceinline__ int block_incl_scan_int(int v, int* wsum, int lane, int wid) {
    #pragma unroll
    for (int off = 1; off < 32; off <<= 1) {
        int n = __shfl_up_sync(0xffffffffu, v, off);
        if (lane >= off) v += n;
    }
    if (lane == 31) wsum[wid] = v;
    __syncthreads();
    if (wid == 0) {
        int w = wsum[lane];
        #pragma unroll
        for (int off = 1; off < 32; off <<= 1) {
            int n = __shfl_up_sync(0xffffffffu, w, off);
            if (lane >= off) w += n;
        }
        wsum[lane] = w;
    }
    __syncthreads();
    return v + (wid ? wsum[wid - 1] : 0);
}

// ---------------- Kernel 1: threshold -> fused stats+gather pass ----------------
__global__ void __launch_bounds__(NT) k_stats(const float* __restrict__ logits,
                                              const float* __restrict__ temps, int V)
{
    const int row = blockIdx.x;
    const int tid = threadIdx.x;
    const int lane = tid & 31, wid = tid >> 5;
    __shared__ int   hist[NBINS];
    __shared__ float wred[32];
    __shared__ int   iwsum[32];
    __shared__ float s_S, s_shift;
    __shared__ int   s_bt, s_cnt;

    const float* lrow = logits + (size_t)row * V;
    const float invT = 1.0f / temps[row];
    const int need = V < 1024 ? V : 1024;
    const int V4 = V >> 2;
    const float4* l4 = (const float4*)lrow;

    // ---- Phase B FIRST: 16k-point coalesced subsample histogram -> threshold ----
    if (V > CAP) {
        for (int t = tid; t < NBINS; t += NT) hist[t] = 0;
        __syncthreads();
        int step4 = V4 / 4096; if (step4 < 1) step4 = 1;
        int ns4 = V4 / step4; if (ns4 > 4096) ns4 = 4096;
        int subN = ns4 * 4;
        for (int j = tid; j < ns4; j += NT) {
            float4 v = l4[(size_t)j * step4];
            if (v.x > 2.0f) atomicAdd(&hist[bin_of(v.x)], 1);
            if (v.y > 2.0f) atomicAdd(&hist[bin_of(v.y)], 1);
            if (v.z > 2.0f) atomicAdd(&hist[bin_of(v.z)], 1);
            if (v.w > 2.0f) atomicAdd(&hist[bin_of(v.w)], 1);
        }
        if (tid == 0) { s_bt = 1024; s_cnt = 0; }
        __syncthreads();
        // target expected true count ~1.55*need (>=4 sigma inside [1024, 2048])
        int tgt = (int)(((long long)need * 31LL * subN) / (20LL * (long long)V));
        if (tgt < 1) tgt = 1;
        int b = 2047 - tid;                       // bins 1088..2047 over 960 threads
        int v = (tid < 960) ? hist[b] : 0;
        int sfx = block_incl_scan_int(v, iwsum, lane, wid);
        if (tid < 960 && sfx >= tgt && sfx - v < tgt) s_bt = b;
        __syncthreads();
    } else if (tid == 0) { s_cnt = 0; }
    __syncthreads();

    // ---- Fused single full pass: max + sum(__expf) + candidate gather ----
    const float xthr = (V > CAP) ? ((float)s_bt * 0.03125f - 32.0f) : -FLT_MAX;
    float s = 0.f, s2 = 0.f, mx = -FLT_MAX;
    int i = tid;
    for (; i + NT < V4; i += 2 * NT) {
        float4 v0 = l4[i];
        float4 v1 = l4[i + NT];
        mx = fmaxf(mx, fmaxf(fmaxf(v0.x, v0.y), fmaxf(v0.z, v0.w)));
        mx = fmaxf(mx, fmaxf(fmaxf(v1.x, v1.y), fmaxf(v1.z, v1.w)));
        s  += __expf(v0.x * invT) + __expf(v0.y * invT) + __expf(v0.z * invT) + __expf(v0.w * invT);
        s2 += __expf(v1.x * invT) + __expf(v1.y * invT) + __expf(v1.z * invT) + __expf(v1.w * invT);
        #pragma unroll
        for (int c = 0; c < 4; c++) {
            float x = (c == 0) ? v0.x : (c == 1) ? v0.y : (c == 2) ? v0.z : v0.w;
            if (x >= xthr) {
                int pos = atomicAdd(&s_cnt, 1);
                if (pos < CAP) { g_cval[row * CAP + pos] = x; g_cidx[row * CAP + pos] = (i << 2) + c; }
            }
        }
        #pragma unroll
        for (int c = 0; c < 4; c++) {
            float x = (c == 0) ? v1.x : (c == 1) ? v1.y : (c == 2) ? v1.z : v1.w;
            if (x >= xthr) {
                int pos = atomicAdd(&s_cnt, 1);
                if (pos < CAP) { g_cval[row * CAP + pos] = x; g_cidx[row * CAP + pos] = ((i + NT) << 2) + c; }
            }
        }
    }
    for (; i < V4; i += NT) {
        float4 v = l4[i];
        mx = fmaxf(mx, fmaxf(fmaxf(v.x, v.y), fmaxf(v.z, v.w)));
        s += __expf(v.x * invT) + __expf(v.y * invT) + __expf(v.z * invT) + __expf(v.w * invT);
        #pragma unroll
        for (int c = 0; c < 4; c++) {
            float x = (c == 0) ? v.x : (c == 1) ? v.y : (c == 2) ? v.z : v.w;
            if (x >= xthr) {
                int pos = atomicAdd(&s_cnt, 1);
                if (pos < CAP) { g_cval[row * CAP + pos] = x; g_cidx[row * CAP + pos] = (i << 2) + c; }
            }
        }
    }
    s += s2;
    for (int t = (V4 << 2) + tid; t < V; t += NT) {
        float x = lrow[t];
        mx = fmaxf(mx, x);
        s += __expf(x * invT);
        if (x >= xthr) {
            int pos = atomicAdd(&s_cnt, 1);
            if (pos < CAP) { g_cval[row * CAP + pos] = x; g_cidx[row * CAP + pos] = t; }
        }
    }

    // Reductions
    s = warp_red_sum(s);
    if (lane == 0) wred[wid] = s;
    __syncthreads();
    if (wid == 0) { float t = warp_red_sum(wred[lane]); if (lane == 0) s_S = t; }
    __syncthreads();
    mx = warp_red_max(mx);
    if (lane == 0) wred[wid] = mx;
    __syncthreads();
    if (wid == 0) {
        float t = warp_red_max(wred[lane]);
        if (lane == 0) {
            float mxT = t * invT;
            s_shift = (mxT > 80.f || !isfinite(s_S)) ? mxT : 0.f;
        }
    }
    __syncthreads();
    const float shift = s_shift;
    if (shift != 0.f) {            // rare overflow-safe recompute (precise path)
        s = 0.f;
        for (int t = tid; t < V; t += NT) s += expf(lrow[t] * invT - shift);
        s = warp_red_sum(s);
        if (lane == 0) wred[wid] = s;
        __syncthreads();
        if (wid == 0) { float t = warp_red_sum(wred[lane]); if (lane == 0) s_S = t; }
        __syncthreads();
    }

    // ---- Verify count; rare fallback: exact histogram + re-gather ----
    int cnt = s_cnt;
    if (V > CAP && !(cnt >= need && cnt <= CAP)) {
        for (int t = tid; t < NBINS; t += NT) hist[t] = 0;
        __syncthreads();
        for (int t = tid; t < V; t += NT) atomicAdd(&hist[bin_of(lrow[t])], 1);
        __syncthreads();
        if (tid == 0) {
            int acc = 0, bt2 = 0;
            for (int b = NBINS - 1; b >= 0; b--) {
                int na = acc + hist[b];
                if (na >= need) { bt2 = (na <= CAP) ? b : (b + 1); break; }
                acc = na;
            }
            s_bt = bt2 > 0 ? bt2 - 1 : 0;   // one-bin margin for float-edge compare
            s_cnt = 0;
        }
        __syncthreads();
        const float xt2 = (float)s_bt * 0.03125f - 32.0f;
        for (int t = tid; t < V; t += NT) {
            float x = lrow[t];
            if (x >= xt2) {
                int pos = atomicAdd(&s_cnt, 1);
                if (pos < CAP) { g_cval[row * CAP + pos] = x; g_cidx[row * CAP + pos] = t; }
            }
        }
        __syncthreads();
        cnt = s_cnt;
    }
    if (tid == 0) {
        g_cnt[row]   = cnt < CAP ? cnt : CAP;
        g_sum[row]   = s_S;
        g_shift[row] = shift;
    }
}

// ---------------- Sort helpers: 32-bit key + 32-bit payload ----------------
__device__ __forceinline__ bool kv_gt(unsigned k1, unsigned p1, unsigned k2, unsigned p2) {
    return (k1 > k2) || (k1 == k2 && p1 > p2);
}
// Register CE via shuffle: element index e, stage K, step j (<=16, in-warp)
__device__ __forceinline__ void ce_shfl(unsigned &k, unsigned &p, int e, int K, int j) {
    unsigned ok = __shfl_xor_sync(0xffffffffu, k, j);
    unsigned op = __shfl_xor_sync(0xffffffffu, p, j);
    bool keepMax = (((e & K) == 0) == ((e & j) == 0));
    bool og = kv_gt(ok, op, k, p);
    if (keepMax == og) { k = ok; p = op; }
}
__device__ __forceinline__ void ce_sh(unsigned* kv, unsigned* pv, int i, int j, int K) {
    unsigned k1 = kv[i], p1 = pv[i], k2 = kv[i + j], p2 = pv[i + j];
    bool sw = ((i & K) == 0) ? kv_gt(k2, p2, k1, p1) : kv_gt(k1, p1, k2, p2);
    if (sw) { kv[i] = k2; pv[i] = p2; kv[i + j] = k1; pv[i + j] = p1; }
}

// ---------------- Kernel 2: zero + sort + masks + sample + scatter ----------------
__global__ void __launch_bounds__(NT) k_sample(const float* __restrict__ temps,
                                               const int*   __restrict__ top_ks,
                                               const float* __restrict__ top_ps,
                                               const float* __restrict__ min_ps,
                                               const float* __restrict__ u,
                                               float* __restrict__ out,
                                               int V, int B, int tokens_first)
{
    const int row = blockIdx.x;
    const int tid = threadIdx.x;
    const int lane = tid & 31, wid = tid >> 5;
    __shared__ unsigned skv[CAP];
    __shared__ unsigned skp[CAP];
    __shared__ float wsum[32];
    __shared__ float sh_p0, sh_tot;

    // Zero this row's output slice first: streaming stores drain under the sort.
    float* probs_out = tokens_first ? (out + B) : out;
    float* prow = probs_out + (size_t)row * V;
    if (((B & 3) == 0 || !tokens_first) && (V & 3) == 0) {
        float4* p4 = (float4*)prow;
        const float4 z4 = make_float4(0.f, 0.f, 0.f, 0.f);
        const int V4 = V >> 2;
        for (int i = tid; i < V4; i += NT) __stcs(p4 + i, z4);
    } else {
        for (int i = tid; i < V; i += NT) __stcs(prow + i, 0.f);
    }

    const int C = g_cnt[row];

    if (C <= 2048) {
        // -------- Hybrid bitonic sort, N=2048, thread t owns {t, t+1024} --------
        unsigned ka = 0u, pa = 0u, kb = 0u, pb = 0u;
        if (tid < C) {
            unsigned fb = __float_as_uint(g_cval[row * CAP + tid]);
            ka = (fb & 0x80000000u) ? ~fb : (fb | 0x80000000u);
            pa = ~(unsigned)g_cidx[row * CAP + tid];
        }
        if (tid + 1024 < C) {
            unsigned fb = __float_as_uint(g_cval[row * CAP + tid + 1024]);
            kb = (fb & 0x80000000u) ? ~fb : (fb | 0x80000000u);
            pb = ~(unsigned)g_cidx[row * CAP + tid + 1024];
        }
        // Stages k=2..32: fully in registers (shfl), no barriers
        #pragma unroll
        for (int K = 2; K <= 32; K <<= 1) {
            #pragma unroll
            for (int j = K >> 1; j >= 1; j >>= 1) {
                ce_shfl(ka, pa, tid, K, j);
                ce_shfl(kb, pb, tid + 1024, K, j);
            }
        }
        // Stages k=64..1024: j>=32 via shared, j<=16 via shfl
        for (int K = 64; K <= 1024; K <<= 1) {
            skv[tid] = ka; skp[tid] = pa; skv[tid + 1024] = kb; skp[tid + 1024] = pb;
            __syncthreads();
            for (int j = K >> 1; j >= 32; j >>= 1) {
                int i = ((tid & ~(j - 1)) << 1) | (tid & (j - 1));
                ce_sh(skv, skp, i, j, K);
                __syncthreads();
            }
            ka = skv[tid]; pa = skp[tid]; kb = skv[tid + 1024]; pb = skp[tid + 1024];
            #pragma unroll
            for (int j = 16; j >= 1; j >>= 1) {
                ce_shfl(ka, pa, tid, K, j);
                ce_shfl(kb, pb, tid + 1024, K, j);
            }
        }
        // Stage k=2048: j=1024 in-thread, j=512..32 shared, j<=16 shfl
        if (kv_gt(kb, pb, ka, pa)) {
            unsigned tk = ka, tp2 = pa; ka = kb; pa = pb; kb = tk; pb = tp2;
        }
        skv[tid] = ka; skp[tid] = pa; skv[tid + 1024] = kb; skp[tid + 1024] = pb;
        __syncthreads();
        for (int j = 512; j >= 32; j >>= 1) {
            int i = ((tid & ~(j - 1)) << 1) | (tid & (j - 1));
            ce_sh(skv, skp, i, j, 2048);
            __syncthreads();
        }
        ka = skv[tid]; pa = skp[tid];
        #pragma unroll
        for (int j = 16; j >= 1; j >>= 1) ce_shfl(ka, pa, tid, 2048, j);
        skv[tid] = ka; skp[tid] = pa;   // only ranks < 1024 matter downstream
        __syncthreads();
    } else {
        // -------- Generic fallback: all-shared bitonic on 4096 (rare) --------
        const int npow2 = CAP;
        const int NCE = npow2 >> 1;
        for (int i = tid; i < npow2; i += NT) {
            unsigned key = 0u, pay = 0u;
            if (i < C) {
                unsigned fb = __float_as_uint(g_cval[row * CAP + i]);
                key = (fb & 0x80000000u) ? ~fb : (fb | 0x80000000u);
                pay = ~(unsigned)g_cidx[row * CAP + i];
            }
            skv[i] = key; skp[i] = pay;
        }
        __syncthreads();
        for (int K = 2; K <= npow2; K <<= 1) {
            int j = K >> 1;
            for (; j >= 64; j >>= 1) {
                for (int c = tid; c < NCE; c += NT) {
                    int i = ((c & ~(j - 1)) << 1) | (c & (j - 1));
                    ce_sh(skv, skp, i, j, K);
                }
                __syncthreads();
            }
            for (; j >= 1; j >>= 1) {
                for (int c = tid; c < NCE; c += NT) {
                    int i = ((c & ~(j - 1)) << 1) | (c & (j - 1));
                    ce_sh(skv, skp, i, j, K);
                }
                __syncwarp();
            }
            __syncthreads();
        }
    }

    // ---- Per-rank prob (only first NT ranks can survive: top_k < 1024) ----
    const float invT  = 1.0f / temps[row];
    const float S     = g_sum[row];
    const float shift = g_shift[row];
    float p = 0.f;
    int   myidx = 0;
    if (tid < C) {
        unsigned mu = skv[tid];
        unsigned fb = (mu & 0x80000000u) ? (mu ^ 0x80000000u) : ~mu;
        p = expf(__uint_as_float(fb) * invT - shift) / S;
        myidx = (int)(~skp[tid]);
    }
    if (tid == 0) sh_p0 = p;

    float cumincl = block_incl_scan(p, wsum, lane, wid);   // pre-mask cumsum

    const int   tk  = top_ks[row];
    const float tp  = top_ps[row];
    const float thr = sh_p0 * min_ps[row];
    float q = p;
    if (tid >= tk)        q = 0.f;   // top-k
    if (cumincl - q > tp) q = 0.f;   // top-p (cumsum computed pre-mask)
    if (q < thr)          q = 0.f;   // min-p

    float cq = block_incl_scan(q, wsum, lane, wid);        // post-mask CDF numerator
    if (tid == NT - 1) sh_tot = cq;
    __syncthreads();
    const float tot  = sh_tot;
    const float uval = u[row];

    int rank = __syncthreads_count((cq / tot < uval) ? 1 : 0);
    if (rank > NT - 1) rank = NT - 1;
    if (rank > V - 1) rank = V - 1;

    if (tid == 0 && tokens_first) {
        out[row] = (float)(int)(~skp[rank]);
    }
    if (q > 0.f) {
        prow[myidx] = q / tot;     // ordered after zero-stores by the barriers above
    }
}

extern "C" void kernel_launch(void* const* d_in, const int* in_sizes, int n_in,
                              void* d_out, int out_size)
{
    const float* logits = (const float*)d_in[0];
    const float* temps  = (const float*)d_in[1];
    const int*   topks  = (const int*)  d_in[2];
    const float* topps  = (const float*)d_in[3];
    const float* minps  = (const float*)d_in[4];
    const float* u      = (const float*)d_in[5];

    const int B = in_sizes[1];
    const int V = in_sizes[0] / B;
    float* out = (float*)d_out;
    int tokens_first = (out_size == B + B * V) ? 1 : 0;

    k_stats <<<B, NT>>>(logits, temps, V);
    k_sample<<<B, NT>>>(temps, topks, topps, minps, u, out, V, B, tokens_first);
}

// round 6
// speedup vs baseline: 1.0056x; 1.0056x over previous
#include <cuda_runtime.h>
#include <math.h>
#include <stdint.h>
#include <float.h>

#define MAXB  128
#define CAP   4096
#define NBINS 2048
#define FBINS 4096
#define NT    1024

// Global scratch (no allocations allowed)
__device__ float g_sum[MAXB];
__device__ float g_shift[MAXB];
__device__ float g_mx[MAXB];
__device__ float g_xthr[MAXB];
__device__ int   g_cnt[MAXB];
__device__ float g_cval[MAXB * CAP];
__device__ int   g_cidx[MAXB * CAP];

__device__ __forceinline__ int bin_of(float x) {
    int b = (int)floorf((x + 32.0f) * 32.0f);   // width 1/32 over [-32, 32]
    b = b < 0 ? 0 : b;
    return b > (NBINS - 1) ? (NBINS - 1) : b;
}

__device__ __forceinline__ float warp_red_sum(float v) {
    #pragma unroll
    for (int o = 16; o; o >>= 1) v += __shfl_xor_sync(0xffffffffu, v, o);
    return v;
}
__device__ __forceinline__ float warp_red_max(float v) {
    #pragma unroll
    for (int o = 16; o; o >>= 1) v = fmaxf(v, __shfl_xor_sync(0xffffffffu, v, o));
    return v;
}

__device__ __forceinline__ float block_incl_scan(float v, float* wsum, int lane, int wid) {
    #pragma unroll
    for (int off = 1; off < 32; off <<= 1) {
        float n = __shfl_up_sync(0xffffffffu, v, off);
        if (lane >= off) v += n;
    }
    __syncthreads();
    if (lane == 31) wsum[wid] = v;
    __syncthreads();
    if (wid == 0) {
        float w = wsum[lane];
        #pragma unroll
        for (int off = 1; off < 32; off <<= 1) {
            float n = __shfl_up_sync(0xffffffffu, w, off);
            if (lane >= off) w += n;
        }
        wsum[lane] = w;
    }
    __syncthreads();
    return v + (wid ? wsum[wid - 1] : 0.f);
}

__device__ __forceinline__ int block_incl_scan_int(int v, int* wsum, int lane, int wid) {
    #pragma unroll
    for (int off = 1; off < 32; off <<= 1) {
        int n = __shfl_up_sync(0xffffffffu, v, off);
        if (lane >= off) v += n;
    }
    if (lane == 31) wsum[wid] = v;
    __syncthreads();
    if (wid == 0) {
        int w = wsum[lane];
        #pragma unroll
        for (int off = 1; off < 32; off <<= 1) {
            int n = __shfl_up_sync(0xffffffffu, w, off);
            if (lane >= off) w += n;
        }
        wsum[lane] = w;
    }
    __syncthreads();
    return v + (wid ? wsum[wid - 1] : 0);
}

// map float -> order-preserving u32; and back
__device__ __forceinline__ unsigned fmap(float x) {
    unsigned fb = __float_as_uint(x);
    return (fb & 0x80000000u) ? ~fb : (fb | 0x80000000u);
}
__device__ __forceinline__ float funmap(unsigned mu) {
    unsigned fb = (mu & 0x80000000u) ? (mu & 0x7FFFFFFFu) : ~mu;
    return __uint_as_float(fb);
}

// ---------------- Kernel 1: zero outputs + threshold + fused stats/gather ----------------
__global__ void __launch_bounds__(NT) k_stats(const float* __restrict__ logits,
                                              const float* __restrict__ temps,
                                              float* __restrict__ out,
                                              int V, int B, int tokens_first)
{
    const int row = blockIdx.x;
    const int tid = threadIdx.x;
    const int lane = tid & 31, wid = tid >> 5;
    __shared__ int   hist[NBINS];
    __shared__ float wred[32];
    __shared__ int   iwsum[32];
    __shared__ float s_S, s_shift, s_mxraw;
    __shared__ int   s_bt, s_cnt;

    // ---- Zero this row's norm_probs slice (streaming stores, drain under compute) ----
    {
        float* probs_out = tokens_first ? (out + B) : out;
        float* prow = probs_out + (size_t)row * V;
        if ((V & 3) == 0 && ((B & 3) == 0 || !tokens_first)) {
            float4* p4 = (float4*)prow;
            const float4 z4 = make_float4(0.f, 0.f, 0.f, 0.f);
            for (int i = tid; i < (V >> 2); i += NT) __stcs(p4 + i, z4);
        } else {
            for (int i = tid; i < V; i += NT) __stcs(prow + i, 0.f);
        }
    }

    const float* lrow = logits + (size_t)row * V;
    const float invT = 1.0f / temps[row];
    const int need = V < 1024 ? V : 1024;
    const int V4 = V >> 2;
    const float4* l4 = (const float4*)lrow;

    // ---- 16k-point coalesced subsample histogram -> threshold ----
    if (V > CAP) {
        for (int t = tid; t < NBINS; t += NT) hist[t] = 0;
        __syncthreads();
        int step4 = V4 / 4096; if (step4 < 1) step4 = 1;
        int ns4 = V4 / step4; if (ns4 > 4096) ns4 = 4096;
        int subN = ns4 * 4;
        for (int j = tid; j < ns4; j += NT) {
            float4 v = l4[(size_t)j * step4];
            if (v.x > 2.0f) atomicAdd(&hist[bin_of(v.x)], 1);
            if (v.y > 2.0f) atomicAdd(&hist[bin_of(v.y)], 1);
            if (v.z > 2.0f) atomicAdd(&hist[bin_of(v.z)], 1);
            if (v.w > 2.0f) atomicAdd(&hist[bin_of(v.w)], 1);
        }
        if (tid == 0) { s_bt = 1024; s_cnt = 0; }
        __syncthreads();
        int tgt = (int)(((long long)need * 31LL * subN) / (20LL * (long long)V));
        if (tgt < 1) tgt = 1;
        int b = 2047 - tid;
        int v = (tid < 960) ? hist[b] : 0;
        int sfx = block_incl_scan_int(v, iwsum, lane, wid);
        if (tid < 960 && sfx >= tgt && sfx - v < tgt) s_bt = b;
        __syncthreads();
    } else if (tid == 0) { s_cnt = 0; }
    __syncthreads();

    // ---- Fused full pass: max + sum(__expf) + candidate gather ----
    float xthr = (V > CAP) ? ((float)s_bt * 0.03125f - 32.0f) : -FLT_MAX;
    float s = 0.f, s2 = 0.f, mx = -FLT_MAX;
    int i = tid;
    for (; i + NT < V4; i += 2 * NT) {
        float4 v0 = l4[i];
        float4 v1 = l4[i + NT];
        mx = fmaxf(mx, fmaxf(fmaxf(v0.x, v0.y), fmaxf(v0.z, v0.w)));
        mx = fmaxf(mx, fmaxf(fmaxf(v1.x, v1.y), fmaxf(v1.z, v1.w)));
        s  += __expf(v0.x * invT) + __expf(v0.y * invT) + __expf(v0.z * invT) + __expf(v0.w * invT);
        s2 += __expf(v1.x * invT) + __expf(v1.y * invT) + __expf(v1.z * invT) + __expf(v1.w * invT);
        #pragma unroll
        for (int c = 0; c < 4; c++) {
            float x = (c == 0) ? v0.x : (c == 1) ? v0.y : (c == 2) ? v0.z : v0.w;
            if (x >= xthr) {
                int pos = atomicAdd(&s_cnt, 1);
                if (pos < CAP) { g_cval[row * CAP + pos] = x; g_cidx[row * CAP + pos] = (i << 2) + c; }
            }
        }
        #pragma unroll
        for (int c = 0; c < 4; c++) {
            float x = (c == 0) ? v1.x : (c == 1) ? v1.y : (c == 2) ? v1.z : v1.w;
            if (x >= xthr) {
                int pos = atomicAdd(&s_cnt, 1);
                if (pos < CAP) { g_cval[row * CAP + pos] = x; g_cidx[row * CAP + pos] = ((i + NT) << 2) + c; }
            }
        }
    }
    for (; i < V4; i += NT) {
        float4 v = l4[i];
        mx = fmaxf(mx, fmaxf(fmaxf(v.x, v.y), fmaxf(v.z, v.w)));
        s += __expf(v.x * invT) + __expf(v.y * invT) + __expf(v.z * invT) + __expf(v.w * invT);
        #pragma unroll
        for (int c = 0; c < 4; c++) {
            float x = (c == 0) ? v.x : (c == 1) ? v.y : (c == 2) ? v.z : v.w;
            if (x >= xthr) {
                int pos = atomicAdd(&s_cnt, 1);
                if (pos < CAP) { g_cval[row * CAP + pos] = x; g_cidx[row * CAP + pos] = (i << 2) + c; }
            }
        }
    }
    s += s2;
    for (int t = (V4 << 2) + tid; t < V; t += NT) {
        float x = lrow[t];
        mx = fmaxf(mx, x);
        s += __expf(x * invT);
        if (x >= xthr) {
            int pos = atomicAdd(&s_cnt, 1);
            if (pos < CAP) { g_cval[row * CAP + pos] = x; g_cidx[row * CAP + pos] = t; }
        }
    }

    // Reductions
    s = warp_red_sum(s);
    if (lane == 0) wred[wid] = s;
    __syncthreads();
    if (wid == 0) { float t = warp_red_sum(wred[lane]); if (lane == 0) s_S = t; }
    __syncthreads();
    mx = warp_red_max(mx);
    if (lane == 0) wred[wid] = mx;
    __syncthreads();
    if (wid == 0) {
        float t = warp_red_max(wred[lane]);
        if (lane == 0) {
            s_mxraw = t;
            float mxT = t * invT;
            s_shift = (mxT > 80.f || !isfinite(s_S)) ? mxT : 0.f;
        }
    }
    __syncthreads();
    const float shift = s_shift;
    if (shift != 0.f) {            // rare overflow-safe recompute (precise path)
        s = 0.f;
        for (int t = tid; t < V; t += NT) s += expf(lrow[t] * invT - shift);
        s = warp_red_sum(s);
        if (lane == 0) wred[wid] = s;
        __syncthreads();
        if (wid == 0) { float t = warp_red_sum(wred[lane]); if (lane == 0) s_S = t; }
        __syncthreads();
    }

    // ---- Verify count; rare fallback: exact histogram + bin-exact re-gather ----
    int cnt = s_cnt;
    if (V > CAP && !(cnt >= need && cnt <= CAP)) {
        for (int t = tid; t < NBINS; t += NT) hist[t] = 0;
        __syncthreads();
        for (int t = tid; t < V; t += NT) atomicAdd(&hist[bin_of(lrow[t])], 1);
        __syncthreads();
        if (tid == 0) {
            int acc = 0, bt2 = 0;
            for (int b = NBINS - 1; b >= 0; b--) {
                int na = acc + hist[b];
                if (na >= need) { bt2 = (na <= CAP) ? b : (b + 1); break; }
                acc = na;
            }
            s_bt = bt2;
            s_cnt = 0;
        }
        __syncthreads();
        const int bt2 = s_bt;
        for (int t = tid; t < V; t += NT) {
            float x = lrow[t];
            if (bin_of(x) >= bt2) {                // exact bin compare: cnt <= CAP guaranteed
                int pos = atomicAdd(&s_cnt, 1);
                if (pos < CAP) { g_cval[row * CAP + pos] = x; g_cidx[row * CAP + pos] = t; }
            }
        }
        __syncthreads();
        cnt = s_cnt;
        xthr = (float)bt2 * 0.03125f - 32.0f - 0.0625f;  // safe lower bound for binning
    }
    if (tid == 0) {
        g_cnt[row]   = cnt < CAP ? cnt : CAP;
        g_sum[row]   = s_S;
        g_shift[row] = shift;
        g_mx[row]    = s_mxraw;
        g_xthr[row]  = xthr;
    }
}

// ---------------- fallback bitonic helpers (u32 key + u32 payload=idx) ----------------
__device__ __forceinline__ bool kv_gt(unsigned k1, unsigned p1, unsigned k2, unsigned p2) {
    // "greater in sort order": larger key first, then SMALLER idx first
    return (k1 > k2) || (k1 == k2 && p1 < p2);
}
__device__ __forceinline__ void ce_sh(unsigned* kv, unsigned* pv, int i, int j, int K) {
    unsigned k1 = kv[i], p1 = pv[i], k2 = kv[i + j], p2 = pv[i + j];
    bool sw = ((i & K) == 0) ? kv_gt(k2, p2, k1, p1) : kv_gt(k1, p1, k2, p2);
    if (sw) { kv[i] = k2; pv[i] = p2; kv[i + j] = k1; pv[i + j] = p1; }
}

// ---------------- Kernel 2: histogram-rank + masks + sample + scatter ----------------
__global__ void __launch_bounds__(NT) k_sample(const float* __restrict__ temps,
                                               const int*   __restrict__ top_ks,
                                               const float* __restrict__ top_ps,
                                               const float* __restrict__ min_ps,
                                               const float* __restrict__ u,
                                               float* __restrict__ out,
                                               int V, int B, int tokens_first)
{
    const int row = blockIdx.x;
    const int tid = threadIdx.x;
    const int lane = tid & 31, wid = tid >> 5;
    __shared__ unsigned arena[8192];     // 32 KB, aliased by path
    __shared__ float wsum[32];
    __shared__ int   iwsum[32];
    __shared__ float sh_p0, sh_tot;
    __shared__ int   s_bad;

    const int C = g_cnt[row];
    const float lo = g_xthr[row];
    const float hi = g_mx[row];
    float range = hi - lo;

    // fast path pointers: bins[0..4095], skv[4096..6143], skp[6144..8191]
    int*      bins = (int*)arena;
    unsigned* skv  = arena + 4096;
    unsigned* skp  = arena + 6144;
    // fallback pointers: fkv[0..4095], fkp[4096..8191]
    unsigned* fkv  = arena;
    unsigned* fkp  = arena + 4096;

    bool fast = (C <= 2048) && (range > 0.f) && isfinite(range);
    if (tid == 0) s_bad = 0;

    if (fast) {
        const float scale = 4096.0f / range;
        // my candidates
        unsigned k0 = 0, k1 = 0; int i0 = 0, i1 = 0, b0 = -1, b1 = -1;
        float x0 = 0.f, x1 = 0.f;
        if (tid < C)        { x0 = g_cval[row * CAP + tid];        i0 = g_cidx[row * CAP + tid];        k0 = fmap(x0); }
        if (tid + 1024 < C) { x1 = g_cval[row * CAP + tid + 1024]; i1 = g_cidx[row * CAP + tid + 1024]; k1 = fmap(x1); }
        // 1) zero bins
        #pragma unroll
        for (int t = 0; t < 4; t++) bins[tid + t * NT] = 0;
        __syncthreads();
        // 2) count
        if (tid < C)        { b0 = (int)((x0 - lo) * scale); b0 = b0 < 0 ? 0 : (b0 > 4095 ? 4095 : b0); atomicAdd(&bins[b0], 1); }
        if (tid + 1024 < C) { b1 = (int)((x1 - lo) * scale); b1 = b1 < 0 ? 0 : (b1 > 4095 ? 4095 : b1); atomicAdd(&bins[b1], 1); }
        __syncthreads();
        // 3) suffix-scan: rank_base[b] = #candidates in bins > b  (descending order scan)
        int c0c = bins[4095 - 4 * tid];
        int c1c = bins[4094 - 4 * tid];
        int c2c = bins[4093 - 4 * tid];
        int c3c = bins[4092 - 4 * tid];
        int tot = c0c + c1c + c2c + c3c;
        int base = block_incl_scan_int(tot, iwsum, lane, wid) - tot;   // exclusive over threads
        // write back exclusive bases (in descending-bin order)
        bins[4095 - 4 * tid] = base;
        bins[4094 - 4 * tid] = base + c0c;
        bins[4093 - 4 * tid] = base + c0c + c1c;
        bins[4092 - 4 * tid] = base + c0c + c1c + c2c;
        __syncthreads();
        // 4) scatter to rank slots (post-increment base)
        if (tid < C)        { int sl = atomicAdd(&bins[b0], 1); skv[sl] = k0; skp[sl] = (unsigned)i0; }
        if (tid + 1024 < C) { int sl = atomicAdd(&bins[b1], 1); skv[sl] = k1; skp[sl] = (unsigned)i1; }
        __syncthreads();
        // 5) fix within-bin order: contiguous runs of same bin; tiny insertion sorts
        #pragma unroll
        for (int e = 0; e < 2; e++) {
            int i = tid + e * 1024;
            if (i < C) {
                int bi = (int)((funmap(skv[i]) - lo) * scale); bi = bi < 0 ? 0 : (bi > 4095 ? 4095 : bi);
                int bp = -1;
                if (i > 0) {
                    bp = (int)((funmap(skv[i - 1]) - lo) * scale); bp = bp < 0 ? 0 : (bp > 4095 ? 4095 : bp);
                }
                if (bi != bp) {                       // run start
                    int L = 1;
                    while (i + L < C && L <= 16) {
                        int bn = (int)((funmap(skv[i + L]) - lo) * scale); bn = bn < 0 ? 0 : (bn > 4095 ? 4095 : bn);
                        if (bn != bi) break;
                        L++;
                    }
                    if (L > 16) { atomicExch(&s_bad, 1); }
                    else if (L > 1) {
                        unsigned lk[16], lp[16];
                        for (int t = 0; t < L; t++) { lk[t] = skv[i + t]; lp[t] = skp[i + t]; }
                        for (int a = 1; a < L; a++) {
                            unsigned ck = lk[a], cp = lp[a];
                            int b2 = a - 1;
                            while (b2 >= 0 && !kv_gt(lk[b2], lp[b2], ck, cp)) {
                                lk[b2 + 1] = lk[b2]; lp[b2 + 1] = lp[b2]; b2--;
                            }
                            lk[b2 + 1] = ck; lp[b2 + 1] = cp;
                        }
                        for (int t = 0; t < L; t++) { skv[i + t] = lk[t]; skp[i + t] = lp[t]; }
                    }
                }
            }
        }
        __syncthreads();
        if (s_bad) fast = false;
        __syncthreads();
    }

    if (!fast) {
        // -------- exact bitonic on 4096 (rare) --------
        const int npow2 = CAP;
        const int NCE = npow2 >> 1;
        for (int i = tid; i < npow2; i += NT) {
            unsigned key = 0u, pay = 0xFFFFFFFFu;
            if (i < C) { key = fmap(g_cval[row * CAP + i]); pay = (unsigned)g_cidx[row * CAP + i]; }
            fkv[i] = key; fkp[i] = pay;
        }
        __syncthreads();
        for (int K = 2; K <= npow2; K <<= 1) {
            int j = K >> 1;
            for (; j >= 64; j >>= 1) {
                for (int c = tid; c < NCE; c += NT) {
                    int i = ((c & ~(j - 1)) << 1) | (c & (j - 1));
                    ce_sh(fkv, fkp, i, j, K);
                }
                __syncthreads();
            }
            for (; j >= 1; j >>= 1) {
                for (int c = tid; c < NCE; c += NT) {
                    int i = ((c & ~(j - 1)) << 1) | (c & (j - 1));
                    ce_sh(fkv, fkp, i, j, K);
                }
                __syncwarp();
            }
            __syncthreads();
        }
        skv = fkv; skp = fkp;
    }

    // ---- Per-rank prob (only first NT ranks can survive: top_k < 1024) ----
    const float invT  = 1.0f / temps[row];
    const float S     = g_sum[row];
    const float shift = g_shift[row];
    float p = 0.f;
    int   myidx = 0;
    if (tid < C) {
        p = expf(funmap(skv[tid]) * invT - shift) / S;
        myidx = (int)skp[tid];
    }
    if (tid == 0) sh_p0 = p;

    float cumincl = block_incl_scan(p, wsum, lane, wid);   // pre-mask cumsum

    const int   tk  = top_ks[row];
    const float tp  = top_ps[row];
    const float thr = sh_p0 * min_ps[row];
    float q = p;
    if (tid >= tk)        q = 0.f;   // top-k
    if (cumincl - q > tp) q = 0.f;   // top-p (cumsum computed pre-mask)
    if (q < thr)          q = 0.f;   // min-p

    float cq = block_incl_scan(q, wsum, lane, wid);        // post-mask CDF numerator
    if (tid == NT - 1) sh_tot = cq;
    __syncthreads();
    const float tot  = sh_tot;
    const float uval = u[row];

    int rank = __syncthreads_count((cq / tot < uval) ? 1 : 0);
    if (rank > NT - 1) rank = NT - 1;
    if (rank > V - 1) rank = V - 1;

    float* probs_out = tokens_first ? (out + B) : out;
    float* prow = probs_out + (size_t)row * V;
    if (tid == 0 && tokens_first) {
        out[row] = (float)(int)skp[rank];
    }
    if (q > 0.f) {
        prow[myidx] = q / tot;       // row already zeroed by k_stats (prior kernel)
    }
}

extern "C" void kernel_launch(void* const* d_in, const int* in_sizes, int n_in,
                              void* d_out, int out_size)
{
    const float* logits = (const float*)d_in[0];
    const float* temps  = (const float*)d_in[1];
    const int*   topks  = (const int*)  d_in[2];
    const float* topps  = (const float*)d_in[3];
    const float* minps  = (const float*)d_in[4];
    const float* u      = (const float*)d_in[5];

    const int B = in_sizes[1];
    const int V = in_sizes[0] / B;
    float* out = (float*)d_out;
    int tokens_first = (out_size == B + B * V) ? 1 : 0;

    k_stats <<<B, NT>>>(logits, temps, out, V, B, tokens_first);
    k_sample<<<B, NT>>>(temps, topks, topps, minps, u, out, V, B, tokens_first);
}